// round 6
// baseline (speedup 1.0000x reference)
#include <cuda_runtime.h>
#include <cstdint>

#define N_NODES 100000
#define N_EDGES 800000
#define C 128
#define HALF_N 50000              // shard split point
#define EDGE_THREADS 512
#define SMEM_BYTES (HALF_N * 4)   // 200000 B per CTA

// Allocation-free scratch: per-node dot products (fp32, 16B-aligned)
__device__ __align__(16) float g_s[N_NODES];   // x_0[i] . att[:C]
__device__ __align__(16) float g_t[N_NODES];   // x_0[i] . att[C:]
__device__ int g_idx_is64;                     // 1 if indices are int64

// ---------------------------------------------------------------------------
// Node kernel (unchanged — measured near DRAM roofline ~7.3 TB/s).
// ---------------------------------------------------------------------------
__global__ void __launch_bounds__(256) node_kernel(
    const float* __restrict__ x, const float* __restrict__ att,
    const unsigned int* __restrict__ src32)
{
    if (blockIdx.x == 0 && threadIdx.x == 0) {
        unsigned int acc = 0;
        #pragma unroll
        for (int i = 0; i < 64; ++i) acc |= src32[2 * i + 1];
        g_idx_is64 = (acc == 0u) ? 1 : 0;
    }

    const int lane = threadIdx.x & 31;
    const int warp = (blockIdx.x * blockDim.x + threadIdx.x) >> 5;
    const int n0 = warp * 4;
    if (n0 >= N_NODES) return;

    const float4 ws = reinterpret_cast<const float4*>(att)[lane];
    const float4 wt = reinterpret_cast<const float4*>(att + C)[lane];

    const float4* xr = reinterpret_cast<const float4*>(x + (size_t)n0 * C);
    const float4 x0 = xr[lane];
    const float4 x1 = xr[32 + lane];
    const float4 x2 = xr[64 + lane];
    const float4 x3 = xr[96 + lane];

    float s0 = x0.x*ws.x + x0.y*ws.y + x0.z*ws.z + x0.w*ws.w;
    float s1 = x1.x*ws.x + x1.y*ws.y + x1.z*ws.z + x1.w*ws.w;
    float s2 = x2.x*ws.x + x2.y*ws.y + x2.z*ws.z + x2.w*ws.w;
    float s3 = x3.x*ws.x + x3.y*ws.y + x3.z*ws.z + x3.w*ws.w;
    float t0 = x0.x*wt.x + x0.y*wt.y + x0.z*wt.z + x0.w*wt.w;
    float t1 = x1.x*wt.x + x1.y*wt.y + x1.z*wt.z + x1.w*wt.w;
    float t2 = x2.x*wt.x + x2.y*wt.y + x2.z*wt.z + x2.w*wt.w;
    float t3 = x3.x*wt.x + x3.y*wt.y + x3.z*wt.z + x3.w*wt.w;

    #pragma unroll
    for (int o = 16; o > 0; o >>= 1) {
        s0 += __shfl_xor_sync(0xffffffffu, s0, o);
        s1 += __shfl_xor_sync(0xffffffffu, s1, o);
        s2 += __shfl_xor_sync(0xffffffffu, s2, o);
        s3 += __shfl_xor_sync(0xffffffffu, s3, o);
        t0 += __shfl_xor_sync(0xffffffffu, t0, o);
        t1 += __shfl_xor_sync(0xffffffffu, t1, o);
        t2 += __shfl_xor_sync(0xffffffffu, t2, o);
        t3 += __shfl_xor_sync(0xffffffffu, t3, o);
    }

    if (lane == 0) {
        *reinterpret_cast<float4*>(g_s + n0) = make_float4(s0, s1, s2, s3);
        *reinterpret_cast<float4*>(g_t + n0) = make_float4(t0, t1, t2, t3);
    }
}

// ---------------------------------------------------------------------------
// Edge kernel: 4-CTA cluster, tables sharded across the cluster's smem.
//   rank0: s[0:50K)  rank1: s[50K:100K)  rank2: t[0:50K)  rank3: t[50K:100K)
// Gathers go through the smem crossbar / DSMEM fabric instead of L1tex.
// ---------------------------------------------------------------------------
__device__ __forceinline__ uint32_t smem_u32(const void* p) {
    uint32_t a;
    asm("{ .reg .u64 t; cvta.to.shared.u64 t, %1; cvt.u32.u64 %0, t; }"
        : "=r"(a) : "l"(p));
    return a;
}

__device__ __forceinline__ float dsmem_gather(uint32_t smem_base, int idx, int rank_base) {
    const int big = (idx >= HALF_N) ? 1 : 0;
    const int rank = rank_base + big;
    const uint32_t local = smem_base + (uint32_t)(idx - big * HALF_N) * 4u;
    uint32_t ra;
    asm("mapa.shared::cluster.u32 %0, %1, %2;" : "=r"(ra) : "r"(local), "r"(rank));
    float v;
    asm("ld.shared::cluster.f32 %0, [%1];" : "=f"(v) : "r"(ra));
    return v;
}

__global__ void __launch_bounds__(EDGE_THREADS, 1) __cluster_dims__(4, 1, 1)
edge_cluster_kernel(const void* __restrict__ src, const void* __restrict__ tgt,
                    float* __restrict__ out)
{
    extern __shared__ float sh_tab[];   // 50000 floats (this CTA's shard)
    const int tid = threadIdx.x;

    uint32_t rank;
    asm("mov.u32 %0, %%cluster_ctarank;" : "=r"(rank));

    // --- stage this CTA's shard (coalesced float4 stream)
    const float* gsrc = (rank < 2) ? g_s : g_t;
    const float4* s4 = reinterpret_cast<const float4*>(gsrc + (rank & 1) * HALF_N);
    float4* d4 = reinterpret_cast<float4*>(sh_tab);
    #pragma unroll 4
    for (int i = tid; i < HALF_N / 4; i += EDGE_THREADS) d4[i] = s4[i];

    __syncthreads();
    asm volatile("barrier.cluster.arrive.aligned;" ::: "memory");
    asm volatile("barrier.cluster.wait.aligned;" ::: "memory");

    const uint32_t base = smem_u32(sh_tab);
    const int is64 = g_idx_is64;

    // --- edges: 2 per iteration, grid-stride over pairs
    const int nPairs  = N_EDGES / 2;
    const int gthread = blockIdx.x * EDGE_THREADS + tid;
    const int gstride = gridDim.x * EDGE_THREADS;

    for (int p = gthread; p < nPairs; p += gstride) {
        int si0, si1, ti0, ti1;
        if (is64) {
            const longlong2 a = reinterpret_cast<const longlong2*>(src)[p];
            const longlong2 b = reinterpret_cast<const longlong2*>(tgt)[p];
            si0 = (int)a.x; si1 = (int)a.y;
            ti0 = (int)b.x; ti1 = (int)b.y;
        } else {
            const int2 a = reinterpret_cast<const int2*>(src)[p];
            const int2 b = reinterpret_cast<const int2*>(tgt)[p];
            si0 = a.x; si1 = a.y;
            ti0 = b.x; ti1 = b.y;
        }

        // 4 independent cluster-smem gathers in flight
        const float s0 = dsmem_gather(base, si0, 0);
        const float s1 = dsmem_gather(base, si1, 0);
        const float v0 = dsmem_gather(base, ti0, 2);
        const float v1 = dsmem_gather(base, ti1, 2);

        float2 r;
        r.x = fmaxf(s0 + v0, 0.0f);
        r.y = fmaxf(s1 + v1, 0.0f);
        reinterpret_cast<float2*>(out)[p] = r;
    }

    // no CTA may exit while peers might still read its smem
    __syncthreads();
    asm volatile("barrier.cluster.arrive.aligned;" ::: "memory");
    asm volatile("barrier.cluster.wait.aligned;" ::: "memory");
}

extern "C" void kernel_launch(void* const* d_in, const int* in_sizes, int n_in,
                              void* d_out, int out_size) {
    const float* x_0 = (const float*)d_in[0];
    const void*  src = d_in[1];
    const void*  tgt = d_in[2];
    const float* att = (const float*)d_in[3];
    float* out = (float*)d_out;

    // Node pass: 25000 warps, 8 warps/block -> 3125 blocks (exact)
    node_kernel<<<3125, 256>>>(x_0, att, (const unsigned int*)src);

    // Edge pass: one 200KB-smem CTA per SM, clusters of 4
    cudaFuncSetAttribute(edge_cluster_kernel,
                         cudaFuncAttributeMaxDynamicSharedMemorySize, SMEM_BYTES);

    int dev = 0, sms = 0;
    cudaGetDevice(&dev);
    cudaDeviceGetAttribute(&sms, cudaDevAttrMultiProcessorCount, dev);
    if (sms < 4) sms = 4;
    int clusters = sms / 4;
    int grid = clusters * 4;

    cudaLaunchConfig_t cfg = {};
    cfg.gridDim = dim3((unsigned)grid, 1, 1);
    cfg.blockDim = dim3(EDGE_THREADS, 1, 1);
    cfg.dynamicSmemBytes = SMEM_BYTES;
    cfg.stream = 0;   // legacy default stream (same as <<<>>> above)
    cudaLaunchAttribute attrs[1];
    attrs[0].id = cudaLaunchAttributeClusterDimension;
    attrs[0].val.clusterDim = {4, 1, 1};
    cfg.attrs = attrs;
    cfg.numAttrs = 1;

    cudaLaunchKernelEx(&cfg, edge_cluster_kernel, src, tgt, out);
}

// round 7
// speedup vs baseline: 1.7372x; 1.7372x over previous
#include <cuda_runtime.h>
#include <cstdint>

#define N_NODES 100000
#define N_EDGES 800000
#define C 128
#define SMEM_N 28672                       // per-table smem window (floats)
#define SMEM_BYTES (2 * SMEM_N * 4)        // 229376 B
#define EDGE_BLOCK 1024

// Allocation-free scratch: per-node dot products (fp32, 16B-aligned)
__device__ __align__(16) float g_s[N_NODES];   // x_0[i] . att[:C]
__device__ __align__(16) float g_t[N_NODES];   // x_0[i] . att[C:]
__device__ int g_idx_is64;                     // 1 if indices are int64

// ---------------------------------------------------------------------------
// Node kernel (unchanged — measured near DRAM roofline).
// ---------------------------------------------------------------------------
__global__ void __launch_bounds__(256) node_kernel(
    const float* __restrict__ x, const float* __restrict__ att,
    const unsigned int* __restrict__ src32)
{
    if (blockIdx.x == 0 && threadIdx.x == 0) {
        unsigned int acc = 0;
        #pragma unroll
        for (int i = 0; i < 64; ++i) acc |= src32[2 * i + 1];
        g_idx_is64 = (acc == 0u) ? 1 : 0;
    }

    const int lane = threadIdx.x & 31;
    const int warp = (blockIdx.x * blockDim.x + threadIdx.x) >> 5;
    const int n0 = warp * 4;
    if (n0 >= N_NODES) return;

    const float4 ws = reinterpret_cast<const float4*>(att)[lane];
    const float4 wt = reinterpret_cast<const float4*>(att + C)[lane];

    const float4* xr = reinterpret_cast<const float4*>(x + (size_t)n0 * C);
    const float4 x0 = xr[lane];
    const float4 x1 = xr[32 + lane];
    const float4 x2 = xr[64 + lane];
    const float4 x3 = xr[96 + lane];

    float s0 = x0.x*ws.x + x0.y*ws.y + x0.z*ws.z + x0.w*ws.w;
    float s1 = x1.x*ws.x + x1.y*ws.y + x1.z*ws.z + x1.w*ws.w;
    float s2 = x2.x*ws.x + x2.y*ws.y + x2.z*ws.z + x2.w*ws.w;
    float s3 = x3.x*ws.x + x3.y*ws.y + x3.z*ws.z + x3.w*ws.w;
    float t0 = x0.x*wt.x + x0.y*wt.y + x0.z*wt.z + x0.w*wt.w;
    float t1 = x1.x*wt.x + x1.y*wt.y + x1.z*wt.z + x1.w*wt.w;
    float t2 = x2.x*wt.x + x2.y*wt.y + x2.z*wt.z + x2.w*wt.w;
    float t3 = x3.x*wt.x + x3.y*wt.y + x3.z*wt.z + x3.w*wt.w;

    #pragma unroll
    for (int o = 16; o > 0; o >>= 1) {
        s0 += __shfl_xor_sync(0xffffffffu, s0, o);
        s1 += __shfl_xor_sync(0xffffffffu, s1, o);
        s2 += __shfl_xor_sync(0xffffffffu, s2, o);
        s3 += __shfl_xor_sync(0xffffffffu, s3, o);
        t0 += __shfl_xor_sync(0xffffffffu, t0, o);
        t1 += __shfl_xor_sync(0xffffffffu, t1, o);
        t2 += __shfl_xor_sync(0xffffffffu, t2, o);
        t3 += __shfl_xor_sync(0xffffffffu, t3, o);
    }

    if (lane == 0) {
        *reinterpret_cast<float4*>(g_s + n0) = make_float4(s0, s1, s2, s3);
        *reinterpret_cast<float4*>(g_t + n0) = make_float4(t0, t1, t2, t3);
    }
}

// ---------------------------------------------------------------------------
// Edge kernel: hybrid gather. s[0:SMEM_N) and t[0:SMEM_N) live in CTA-local
// smem (staged via cp.async.bulk / TMA path); indices below SMEM_N use the
// LDS pipe, the rest use L1tex. Single predicated asm block per gather —
// no branches, and the LDG's active-lane count shrinks its line touches.
// ---------------------------------------------------------------------------
__device__ __forceinline__ float gather_mix(const float* __restrict__ gtab,
                                            uint32_t sbase, int idx) {
    float v;
    const float* ga = gtab + idx;
    const uint32_t sa = sbase + ((uint32_t)idx << 2);
    asm("{ .reg .pred p;\n\t"
        "setp.lt.s32 p, %1, %2;\n\t"
        "@p  ld.shared.f32 %0, [%3];\n\t"
        "@!p ld.global.nc.f32 %0, [%4]; }"
        : "=f"(v)
        : "r"(idx), "r"((int)SMEM_N), "r"(sa), "l"(ga));
    return v;
}

__global__ void __launch_bounds__(EDGE_BLOCK, 1) edge_kernel(
    const void* __restrict__ src, const void* __restrict__ tgt,
    float* __restrict__ out)
{
    extern __shared__ __align__(16) float sh[];   // [0:SMEM_N)=s, [SMEM_N:2*SMEM_N)=t
    __shared__ __align__(8) uint64_t mbar;

    const int tid = threadIdx.x;

    if (tid == 0) {
        uint32_t mb;
        asm("{ .reg .u64 t; cvta.to.shared.u64 t, %1; cvt.u32.u64 %0, t; }"
            : "=r"(mb) : "l"(&mbar));
        asm volatile("mbarrier.init.shared.b64 [%0], 1;" :: "r"(mb) : "memory");
    }
    __syncthreads();

    uint32_t mb, sb;
    asm("{ .reg .u64 t; cvta.to.shared.u64 t, %1; cvt.u32.u64 %0, t; }"
        : "=r"(mb) : "l"(&mbar));
    asm("{ .reg .u64 t; cvta.to.shared.u64 t, %1; cvt.u32.u64 %0, t; }"
        : "=r"(sb) : "l"(sh));

    if (tid == 0) {
        asm volatile("mbarrier.arrive.expect_tx.shared.b64 _, [%0], %1;"
                     :: "r"(mb), "r"((uint32_t)SMEM_BYTES) : "memory");
        asm volatile("cp.async.bulk.shared::cluster.global.mbarrier::complete_tx::bytes "
                     "[%0], [%1], %2, [%3];"
                     :: "r"(sb), "l"((const void*)g_s),
                        "r"((uint32_t)(SMEM_N * 4)), "r"(mb) : "memory");
        asm volatile("cp.async.bulk.shared::cluster.global.mbarrier::complete_tx::bytes "
                     "[%0], [%1], %2, [%3];"
                     :: "r"(sb + SMEM_N * 4), "l"((const void*)g_t),
                        "r"((uint32_t)(SMEM_N * 4)), "r"(mb) : "memory");
    }

    // wait for smem tables
    {
        uint32_t done;
        asm volatile(
            "{ .reg .pred p;\n\t"
            "mbarrier.try_wait.parity.shared.b64 p, [%1], 0;\n\t"
            "selp.b32 %0, 1, 0, p; }"
            : "=r"(done) : "r"(mb) : "memory");
        while (!done) {
            asm volatile(
                "{ .reg .pred p;\n\t"
                "mbarrier.try_wait.parity.shared.b64 p, [%1], 0, 0x989680;\n\t"
                "selp.b32 %0, 1, 0, p; }"
                : "=r"(done) : "r"(mb) : "memory");
        }
    }

    const int is64 = g_idx_is64;
    const uint32_t sb_t = sb + SMEM_N * 4;

    const int nPairs  = N_EDGES / 2;
    const int gthread = blockIdx.x * EDGE_BLOCK + tid;
    const int gstride = gridDim.x * EDGE_BLOCK;

    for (int p = gthread; p < nPairs; p += gstride) {
        int si0, si1, ti0, ti1;
        if (is64) {
            const longlong2 a = reinterpret_cast<const longlong2*>(src)[p];
            const longlong2 b = reinterpret_cast<const longlong2*>(tgt)[p];
            si0 = (int)a.x; si1 = (int)a.y;
            ti0 = (int)b.x; ti1 = (int)b.y;
        } else {
            const int2 a = reinterpret_cast<const int2*>(src)[p];
            const int2 b = reinterpret_cast<const int2*>(tgt)[p];
            si0 = a.x; si1 = a.y;
            ti0 = b.x; ti1 = b.y;
        }

        const float s0 = gather_mix(g_s, sb, si0);
        const float s1 = gather_mix(g_s, sb, si1);
        const float v0 = gather_mix(g_t, sb_t, ti0);
        const float v1 = gather_mix(g_t, sb_t, ti1);

        float2 r;
        r.x = fmaxf(s0 + v0, 0.0f);
        r.y = fmaxf(s1 + v1, 0.0f);
        reinterpret_cast<float2*>(out)[p] = r;
    }
}

extern "C" void kernel_launch(void* const* d_in, const int* in_sizes, int n_in,
                              void* d_out, int out_size) {
    const float* x_0 = (const float*)d_in[0];
    const void*  src = d_in[1];
    const void*  tgt = d_in[2];
    const float* att = (const float*)d_in[3];
    float* out = (float*)d_out;

    // Node pass: 25000 warps, 8 warps/block -> 3125 blocks (exact)
    node_kernel<<<3125, 256>>>(x_0, att, (const unsigned int*)src);

    // Edge pass: one 224KB-smem CTA per SM
    cudaFuncSetAttribute(edge_kernel,
                         cudaFuncAttributeMaxDynamicSharedMemorySize, SMEM_BYTES);
    int dev = 0, sms = 0;
    cudaGetDevice(&dev);
    cudaDeviceGetAttribute(&sms, cudaDevAttrMultiProcessorCount, dev);
    if (sms < 1) sms = 148;

    edge_kernel<<<sms, EDGE_BLOCK, SMEM_BYTES>>>(src, tgt, out);
}

// round 8
// speedup vs baseline: 2.3007x; 1.3243x over previous
#include <cuda_runtime.h>
#include <cstdint>

#define N_NODES 100000
#define N_EDGES 800000
#define C 128

// Allocation-free scratch: per-node dot products (fp32, 16B-aligned)
__device__ __align__(16) float g_s[N_NODES];   // x_0[i] . att[:C]
__device__ __align__(16) float g_t[N_NODES];   // x_0[i] . att[C:]

// ---------------------------------------------------------------------------
// Node kernel (R4 shape, measured at HBM roofline). Each block signals PDL
// dependents as it finishes so the edge kernel can start in the tail.
// ---------------------------------------------------------------------------
__global__ void __launch_bounds__(256) node_kernel(
    const float* __restrict__ x, const float* __restrict__ att)
{
    const int lane = threadIdx.x & 31;
    const int warp = (blockIdx.x * blockDim.x + threadIdx.x) >> 5;  // 0..24999
    const int n0 = warp * 4;

    if (n0 < N_NODES) {
        const float4 ws = reinterpret_cast<const float4*>(att)[lane];
        const float4 wt = reinterpret_cast<const float4*>(att + C)[lane];

        const float4* xr = reinterpret_cast<const float4*>(x + (size_t)n0 * C);
        const float4 x0 = xr[lane];
        const float4 x1 = xr[32 + lane];
        const float4 x2 = xr[64 + lane];
        const float4 x3 = xr[96 + lane];

        float s0 = x0.x*ws.x + x0.y*ws.y + x0.z*ws.z + x0.w*ws.w;
        float s1 = x1.x*ws.x + x1.y*ws.y + x1.z*ws.z + x1.w*ws.w;
        float s2 = x2.x*ws.x + x2.y*ws.y + x2.z*ws.z + x2.w*ws.w;
        float s3 = x3.x*ws.x + x3.y*ws.y + x3.z*ws.z + x3.w*ws.w;
        float t0 = x0.x*wt.x + x0.y*wt.y + x0.z*wt.z + x0.w*wt.w;
        float t1 = x1.x*wt.x + x1.y*wt.y + x1.z*wt.z + x1.w*wt.w;
        float t2 = x2.x*wt.x + x2.y*wt.y + x2.z*wt.z + x2.w*wt.w;
        float t3 = x3.x*wt.x + x3.y*wt.y + x3.z*wt.z + x3.w*wt.w;

        #pragma unroll
        for (int o = 16; o > 0; o >>= 1) {
            s0 += __shfl_xor_sync(0xffffffffu, s0, o);
            s1 += __shfl_xor_sync(0xffffffffu, s1, o);
            s2 += __shfl_xor_sync(0xffffffffu, s2, o);
            s3 += __shfl_xor_sync(0xffffffffu, s3, o);
            t0 += __shfl_xor_sync(0xffffffffu, t0, o);
            t1 += __shfl_xor_sync(0xffffffffu, t1, o);
            t2 += __shfl_xor_sync(0xffffffffu, t2, o);
            t3 += __shfl_xor_sync(0xffffffffu, t3, o);
        }

        if (lane == 0) {
            *reinterpret_cast<float4*>(g_s + n0) = make_float4(s0, s1, s2, s3);
            *reinterpret_cast<float4*>(g_t + n0) = make_float4(t0, t1, t2, t3);
        }
    }

    // Let dependent (edge) kernel start scheduling as blocks drain.
    asm volatile("griddepcontrol.launch_dependents;" ::: "memory");
}

// ---------------------------------------------------------------------------
// Edge kernel (R4 shape: 2 edges/thread, 400K threads). PDL: the dtype
// detect and the coalesced index loads read only src/tgt (no dependency on
// node output), so they run BEFORE griddepcontrol.wait, overlapped with the
// node kernel's tail. Gathers happen after the wait.
// ---------------------------------------------------------------------------
__global__ void __launch_bounds__(256) edge_kernel(
    const void* __restrict__ src, const void* __restrict__ tgt,
    float* __restrict__ out)
{
    const int t = blockIdx.x * blockDim.x + threadIdx.x;
    const bool active = (t < N_EDGES / 2);

    // Per-warp idx dtype detect (reads src only): int64 values < 2^31 have
    // all-zero high words; 32 random int32 indices all being zero ~ impossible.
    const int lane = threadIdx.x & 31;
    const unsigned int hw = reinterpret_cast<const unsigned int*>(src)[2 * lane + 1];
    const bool is64 = __all_sync(0xffffffffu, hw == 0u);

    int si0 = 0, si1 = 0, ti0 = 0, ti1 = 0;
    if (active) {
        if (is64) {
            const longlong2 a = reinterpret_cast<const longlong2*>(src)[t];
            const longlong2 b = reinterpret_cast<const longlong2*>(tgt)[t];
            si0 = (int)a.x; si1 = (int)a.y;
            ti0 = (int)b.x; ti1 = (int)b.y;
        } else {
            const int2 a = reinterpret_cast<const int2*>(src)[t];
            const int2 b = reinterpret_cast<const int2*>(tgt)[t];
            si0 = a.x; si1 = a.y;
            ti0 = b.x; ti1 = b.y;
        }
    }

    // Wait for the node kernel's g_s/g_t to be complete and visible.
    asm volatile("griddepcontrol.wait;" ::: "memory");

    if (!active) return;

    // 4 independent L2-hit gathers in flight
    const float s0 = __ldg(g_s + si0);
    const float s1 = __ldg(g_s + si1);
    const float v0 = __ldg(g_t + ti0);
    const float v1 = __ldg(g_t + ti1);

    float2 r;
    r.x = fmaxf(s0 + v0, 0.0f);
    r.y = fmaxf(s1 + v1, 0.0f);
    reinterpret_cast<float2*>(out)[t] = r;
}

extern "C" void kernel_launch(void* const* d_in, const int* in_sizes, int n_in,
                              void* d_out, int out_size) {
    const float* x_0 = (const float*)d_in[0];
    const void*  src = d_in[1];
    const void*  tgt = d_in[2];
    const float* att = (const float*)d_in[3];
    float* out = (float*)d_out;

    // Node pass: 25000 warps, 8 warps/block -> 3125 blocks (exact)
    node_kernel<<<3125, 256>>>(x_0, att);

    // Edge pass: PDL — launches into the node kernel's tail.
    cudaLaunchConfig_t cfg = {};
    cfg.gridDim  = dim3((N_EDGES / 2 + 255) / 256, 1, 1);   // 1563
    cfg.blockDim = dim3(256, 1, 1);
    cfg.dynamicSmemBytes = 0;
    cfg.stream = 0;   // same (legacy default) stream as node_kernel
    cudaLaunchAttribute attrs[1];
    attrs[0].id = cudaLaunchAttributeProgrammaticStreamSerialization;
    attrs[0].val.programmaticStreamSerializationAllowed = 1;
    cfg.attrs = attrs;
    cfg.numAttrs = 1;

    cudaLaunchKernelEx(&cfg, edge_kernel, src, tgt, out);
}